// round 1
// baseline (speedup 1.0000x reference)
#include <cuda_runtime.h>

#define NSEQ 8192
#define DIM  1024

// Scratch (module-load statics; no runtime allocation).
__device__ float g_Q[(size_t)NSEQ * DIM];            // 32 MB
__device__ float g_K[(size_t)NSEQ * DIM];            // 32 MB
__device__ float g_V[(size_t)NSEQ * DIM];            // 32 MB
__device__ float g_S[(size_t)NSEQ * NSEQ];           // 256 MB

#define BM 128
#define BN 128
#define BK 16
#define TM 8
#define TN 8
// 256 threads per block; each thread computes an 8x8 micro-tile.

// ---------------------------------------------------------------------------
// NN SGEMM: C[M,N] = alpha * A[M,K] @ B[K,N]   (all row-major)
// causal_klimit: if nonzero, k-loop limited to min(K, (by+1)*BM) — used for
// O = P @ V where P rows beyond the block-diagonal are zero / never needed.
// ---------------------------------------------------------------------------
__global__ void __launch_bounds__(256, 2)
sgemm_nn(const float* __restrict__ A, const float* __restrict__ B,
         float* __restrict__ C, int M, int N, int K,
         int lda, int ldb, int ldc, float alpha, int causal_klimit)
{
    __shared__ float As[BK][BM];
    __shared__ float Bs[BK][BN];

    const int tid  = threadIdx.x;
    const int row0 = blockIdx.y * BM;
    const int col0 = blockIdx.x * BN;

    const int kmax = causal_klimit ? min(K, row0 + BM) : K;

    // A tile: 128x16 = 512 float4. f = tid and tid+256.
    //   m = f>>2, kc = (f&3)*4  (scatter-transpose into As[k][m])
    const int a_m0 = tid >> 2;
    const int a_kc = (tid & 3) * 4;
    const int a_m1 = a_m0 + 64;
    // B tile (NN): 16x128 = 512 float4. k = f>>5, nc = (f&31)*4.
    const int b_k0 = tid >> 5;
    const int b_nc = (tid & 31) * 4;
    const int b_k1 = b_k0 + 8;

    const float* Ab = A + (size_t)row0 * lda;
    const float* Bb = B + col0;

    const int tm = (tid / 16) * TM;
    const int tn = (tid % 16) * TN;

    float acc[TM][TN];
#pragma unroll
    for (int i = 0; i < TM; i++)
#pragma unroll
        for (int j = 0; j < TN; j++) acc[i][j] = 0.f;

    for (int kt = 0; kt < kmax; kt += BK) {
        const float4 a0 = *(const float4*)(Ab + (size_t)a_m0 * lda + kt + a_kc);
        const float4 a1 = *(const float4*)(Ab + (size_t)a_m1 * lda + kt + a_kc);
        const float4 b0 = *(const float4*)(Bb + (size_t)(kt + b_k0) * ldb + b_nc);
        const float4 b1 = *(const float4*)(Bb + (size_t)(kt + b_k1) * ldb + b_nc);

        __syncthreads();   // previous tile's compute done before overwrite

        As[a_kc + 0][a_m0] = a0.x; As[a_kc + 1][a_m0] = a0.y;
        As[a_kc + 2][a_m0] = a0.z; As[a_kc + 3][a_m0] = a0.w;
        As[a_kc + 0][a_m1] = a1.x; As[a_kc + 1][a_m1] = a1.y;
        As[a_kc + 2][a_m1] = a1.z; As[a_kc + 3][a_m1] = a1.w;
        *(float4*)&Bs[b_k0][b_nc] = b0;
        *(float4*)&Bs[b_k1][b_nc] = b1;

        __syncthreads();

#pragma unroll
        for (int kk = 0; kk < BK; kk++) {
            float a[TM], b[TN];
#pragma unroll
            for (int i = 0; i < TM; i++) a[i] = As[kk][tm + i];
#pragma unroll
            for (int j = 0; j < TN; j++) b[j] = Bs[kk][tn + j];
#pragma unroll
            for (int i = 0; i < TM; i++)
#pragma unroll
                for (int j = 0; j < TN; j++) acc[i][j] += a[i] * b[j];
        }
    }

#pragma unroll
    for (int i = 0; i < TM; i++) {
#pragma unroll
        for (int j = 0; j < TN; j += 4) {
            float4 r = make_float4(acc[i][j] * alpha, acc[i][j + 1] * alpha,
                                   acc[i][j + 2] * alpha, acc[i][j + 3] * alpha);
            *(float4*)(C + (size_t)(row0 + tm + i) * ldc + col0 + tn + j) = r;
        }
    }
}

// ---------------------------------------------------------------------------
// NT SGEMM: C[M,N] = alpha * A[M,K] @ B[N,K]^T  (row-major; both K-contiguous)
// Causal: blocks with col0 > row0 are entirely masked — skipped.
// ---------------------------------------------------------------------------
__global__ void __launch_bounds__(256, 2)
sgemm_nt_causal(const float* __restrict__ A, const float* __restrict__ B,
                float* __restrict__ C, int M, int N, int K,
                int lda, int ldb, int ldc, float alpha)
{
    const int row0 = blockIdx.y * BM;
    const int col0 = blockIdx.x * BN;
    if (col0 > row0) return;   // strictly-upper tile: fully masked

    __shared__ float As[BK][BM];
    __shared__ float Bs[BK][BN];

    const int tid = threadIdx.x;

    const int a_m0 = tid >> 2;
    const int a_kc = (tid & 3) * 4;
    const int a_m1 = a_m0 + 64;
    // B tile (NT): rows of B are K-contiguous, same scatter-transpose as A.
    const int b_n0 = a_m0;
    const int b_n1 = a_m1;

    const float* Ab = A + (size_t)row0 * lda;
    const float* Bb = B + (size_t)col0 * ldb;

    const int tm = (tid / 16) * TM;
    const int tn = (tid % 16) * TN;

    float acc[TM][TN];
#pragma unroll
    for (int i = 0; i < TM; i++)
#pragma unroll
        for (int j = 0; j < TN; j++) acc[i][j] = 0.f;

    for (int kt = 0; kt < K; kt += BK) {
        const float4 a0 = *(const float4*)(Ab + (size_t)a_m0 * lda + kt + a_kc);
        const float4 a1 = *(const float4*)(Ab + (size_t)a_m1 * lda + kt + a_kc);
        const float4 b0 = *(const float4*)(Bb + (size_t)b_n0 * ldb + kt + a_kc);
        const float4 b1 = *(const float4*)(Bb + (size_t)b_n1 * ldb + kt + a_kc);

        __syncthreads();

        As[a_kc + 0][a_m0] = a0.x; As[a_kc + 1][a_m0] = a0.y;
        As[a_kc + 2][a_m0] = a0.z; As[a_kc + 3][a_m0] = a0.w;
        As[a_kc + 0][a_m1] = a1.x; As[a_kc + 1][a_m1] = a1.y;
        As[a_kc + 2][a_m1] = a1.z; As[a_kc + 3][a_m1] = a1.w;
        Bs[a_kc + 0][b_n0] = b0.x; Bs[a_kc + 1][b_n0] = b0.y;
        Bs[a_kc + 2][b_n0] = b0.z; Bs[a_kc + 3][b_n0] = b0.w;
        Bs[a_kc + 0][b_n1] = b1.x; Bs[a_kc + 1][b_n1] = b1.y;
        Bs[a_kc + 2][b_n1] = b1.z; Bs[a_kc + 3][b_n1] = b1.w;

        __syncthreads();

#pragma unroll
        for (int kk = 0; kk < BK; kk++) {
            float a[TM], b[TN];
#pragma unroll
            for (int i = 0; i < TM; i++) a[i] = As[kk][tm + i];
#pragma unroll
            for (int j = 0; j < TN; j++) b[j] = Bs[kk][tn + j];
#pragma unroll
            for (int i = 0; i < TM; i++)
#pragma unroll
                for (int j = 0; j < TN; j++) acc[i][j] += a[i] * b[j];
        }
    }

#pragma unroll
    for (int i = 0; i < TM; i++) {
#pragma unroll
        for (int j = 0; j < TN; j += 4) {
            float4 r = make_float4(acc[i][j] * alpha, acc[i][j + 1] * alpha,
                                   acc[i][j + 2] * alpha, acc[i][j + 3] * alpha);
            *(float4*)(C + (size_t)(row0 + tm + i) * ldc + col0 + tn + j) = r;
        }
    }
}

// ---------------------------------------------------------------------------
// Row softmax over causal lower triangle. One block per row.
// Row i: valid cols [0, i]; zero-fill (i, round_up(i+1,128)) so the P@V GEMM
// can run k up to the block-row boundary without masking.
// S already contains scores * (1/sqrt(D_K)).
// ---------------------------------------------------------------------------
__global__ void softmax_rows(float* __restrict__ S)
{
    __shared__ float red[256];
    const int row = blockIdx.x;
    const int tid = threadIdx.x;
    float* srow = S + (size_t)row * NSEQ;
    const int n      = row + 1;
    const int padded = (row & ~127) + 128;

    float m = -1e30f;
    for (int c = tid; c < n; c += 256) m = fmaxf(m, srow[c]);
    red[tid] = m;
    __syncthreads();
    for (int s = 128; s > 0; s >>= 1) {
        if (tid < s) red[tid] = fmaxf(red[tid], red[tid + s]);
        __syncthreads();
    }
    m = red[0];
    __syncthreads();

    float sum = 0.f;
    for (int c = tid; c < n; c += 256) sum += __expf(srow[c] - m);
    red[tid] = sum;
    __syncthreads();
    for (int s = 128; s > 0; s >>= 1) {
        if (tid < s) red[tid] += red[tid + s];
        __syncthreads();
    }
    const float inv = 1.0f / red[0];

    for (int c = tid; c < n; c += 256) srow[c] = __expf(srow[c] - m) * inv;
    for (int c = n + tid; c < padded; c += 256) srow[c] = 0.f;
}

// ---------------------------------------------------------------------------
extern "C" void kernel_launch(void* const* d_in, const int* in_sizes, int n_in,
                              void* d_out, int out_size)
{
    const float* q  = (const float*)d_in[0];
    const float* k  = (const float*)d_in[1];
    const float* v  = (const float*)d_in[2];
    const float* Wq = (const float*)d_in[3];
    const float* Wk = (const float*)d_in[4];
    const float* Wv = (const float*)d_in[5];
    float* out = (float*)d_out;

    float *Q, *K, *V, *S;
    cudaGetSymbolAddress((void**)&Q, g_Q);
    cudaGetSymbolAddress((void**)&K, g_K);
    cudaGetSymbolAddress((void**)&V, g_V);
    cudaGetSymbolAddress((void**)&S, g_S);

    const float inv_sqrt_dk = 0.03125f;   // 1/sqrt(1024)

    dim3 blk(256);
    dim3 grid_proj(DIM / BN, NSEQ / BM);        // (8, 64)
    dim3 grid_sc(NSEQ / BN, NSEQ / BM);         // (64, 64)

    // Projections: Q = q@Wq, K = k@Wk, V = v@Wv
    sgemm_nn<<<grid_proj, blk>>>(q, Wq, Q, NSEQ, DIM, DIM, DIM, DIM, DIM, 1.0f, 0);
    sgemm_nn<<<grid_proj, blk>>>(k, Wk, K, NSEQ, DIM, DIM, DIM, DIM, DIM, 1.0f, 0);
    sgemm_nn<<<grid_proj, blk>>>(v, Wv, V, NSEQ, DIM, DIM, DIM, DIM, DIM, 1.0f, 0);

    // Scores (scaled): S = (Q @ K^T) / sqrt(D_K), lower-tri blocks only
    sgemm_nt_causal<<<grid_sc, blk>>>(Q, K, S, NSEQ, NSEQ, DIM, DIM, DIM, NSEQ,
                                      inv_sqrt_dk);

    // Causal softmax per row (+ zero-pad to 128-block boundary)
    softmax_rows<<<NSEQ, blk>>>(S);

    // Output: O = P @ V, k limited per block row by causality
    sgemm_nn<<<grid_proj, blk>>>(S, V, out, NSEQ, DIM, NSEQ, NSEQ, DIM, DIM,
                                 1.0f, 1);
}

// round 3
// speedup vs baseline: 1.4803x; 1.4803x over previous
#include <cuda_runtime.h>
#include <cuda_bf16.h>
#include <cstdint>

#define NSEQ 8192
#define DIM  1024

// ---------------- scratch (module statics; no runtime allocation) ----------
__device__ float g_Q [(size_t)NSEQ * DIM];
__device__ float g_K [(size_t)NSEQ * DIM];
__device__ float g_V [(size_t)NSEQ * DIM];
__device__ float g_VT[(size_t)DIM  * NSEQ];
__device__ float g_WT[3][(size_t)DIM * DIM];
__device__ float g_S [(size_t)NSEQ * NSEQ];

// ---------------- helpers ---------------------------------------------------
__device__ __forceinline__ uint32_t smem_u32(const void* p) {
    uint32_t a;
    asm("{ .reg .u64 t; cvta.to.shared.u64 t, %1; cvt.u32.u64 %0, t; }"
        : "=r"(a) : "l"(p));
    return a;
}

#define SWZ128(off) ((off) ^ (((off) >> 3) & 0x70))

__device__ __forceinline__ void ldm_x4(uint32_t* r, uint32_t addr) {
    asm volatile("ldmatrix.sync.aligned.m8n8.x4.shared.b16 {%0,%1,%2,%3}, [%4];"
                 : "=r"(r[0]), "=r"(r[1]), "=r"(r[2]), "=r"(r[3]) : "r"(addr));
}
__device__ __forceinline__ void ldm_x2(uint32_t* r, uint32_t addr) {
    asm volatile("ldmatrix.sync.aligned.m8n8.x2.shared.b16 {%0,%1}, [%2];"
                 : "=r"(r[0]), "=r"(r[1]) : "r"(addr));
}
__device__ __forceinline__ void mma_bf16(float* c, const uint32_t* a,
                                         const uint32_t* b) {
    asm volatile(
        "mma.sync.aligned.m16n8k16.row.col.f32.bf16.bf16.f32 "
        "{%0,%1,%2,%3}, {%4,%5,%6,%7}, {%8,%9}, {%0,%1,%2,%3};"
        : "+f"(c[0]), "+f"(c[1]), "+f"(c[2]), "+f"(c[3])
        : "r"(a[0]), "r"(a[1]), "r"(a[2]), "r"(a[3]), "r"(b[0]), "r"(b[1]));
}

// pack two floats to bf16x2 (hi), return residues for the lo slab
__device__ __forceinline__ uint32_t pack_hi(float x, float y,
                                            float& rx, float& ry) {
    __nv_bfloat16 hx = __float2bfloat16_rn(x);
    __nv_bfloat16 hy = __float2bfloat16_rn(y);
    rx = x - __bfloat162float(hx);
    ry = y - __bfloat162float(hy);
    uint16_t ux = *reinterpret_cast<uint16_t*>(&hx);
    uint16_t uy = *reinterpret_cast<uint16_t*>(&hy);
    return (uint32_t)ux | ((uint32_t)uy << 16);
}
__device__ __forceinline__ uint32_t pack_lo(float x, float y) {
    __nv_bfloat16 lx = __float2bfloat16_rn(x);
    __nv_bfloat16 ly = __float2bfloat16_rn(y);
    uint16_t ux = *reinterpret_cast<uint16_t*>(&lx);
    uint16_t uy = *reinterpret_cast<uint16_t*>(&ly);
    return (uint32_t)ux | ((uint32_t)uy << 16);
}

// split 8 floats (two float4) -> hi uint4 + lo uint4 (bf16 pairs, k-ascending)
__device__ __forceinline__ void split8(const float4& a, const float4& b,
                                       uint4& hi, uint4& lo) {
    float r0, r1, r2, r3, r4, r5, r6, r7;
    hi.x = pack_hi(a.x, a.y, r0, r1);
    hi.y = pack_hi(a.z, a.w, r2, r3);
    hi.z = pack_hi(b.x, b.y, r4, r5);
    hi.w = pack_hi(b.z, b.w, r6, r7);
    lo.x = pack_lo(r0, r1);
    lo.y = pack_lo(r2, r3);
    lo.z = pack_lo(r4, r5);
    lo.w = pack_lo(r6, r7);
}

// ---------------------------------------------------------------------------
// bf16x3 NT GEMM on mma.sync: C[M,N] = alpha * A[M,K] @ B[N,K]^T
// A, B row-major with K contiguous. 128x128 CTA tile, 64-elt K chunks,
// double-buffered SMEM with register prefetch of the next chunk.
// mode: 0 plain; 1 causal tile skip (S = Q K^T); 2 causal k-limit (O = P V).
// ---------------------------------------------------------------------------
#define BKF    64                    // K floats per chunk
#define SLABB  (128 * 64 * 2)        // one bf16 slab: 128 rows x 128B = 16 KB
#define STAGEB (4 * SLABB)           // Ah, Al, Bh, Bl = 64 KB
#define SMEM_GEMM_BYTES (2 * STAGEB) // 128 KB

__device__ __forceinline__ void ldg_chunk(
    const float* __restrict__ A, const float* __restrict__ B,
    int lda, int ldb, int row0, int col0, int kt, int tid,
    float4* ar, float4* br)
{
    const int row = tid >> 1;
    const int cb  = (tid & 1) * 8;   // float4 index base within the 64-col row
    const float4* Ap = (const float4*)(A + (size_t)(row0 + row) * lda
                                       + (size_t)kt * BKF) + cb;
    const float4* Bp = (const float4*)(B + (size_t)(col0 + row) * ldb
                                       + (size_t)kt * BKF) + cb;
#pragma unroll
    for (int i = 0; i < 8; i++) { ar[i] = Ap[i]; br[i] = Bp[i]; }
}

__device__ __forceinline__ void sts_chunk(char* smem, int st, int tid,
                                          const float4* ar, const float4* br)
{
    const int row = tid >> 1;
    const int cb  = (tid & 1) * 4;   // 16B-chunk base (8 chunks per 128B row)
    char* base = smem + st * STAGEB;
#pragma unroll
    for (int j = 0; j < 4; j++) {
        const uint32_t off = SWZ128((uint32_t)(row * 128 + (cb + j) * 16));
        uint4 hi, lo;
        split8(ar[2 * j], ar[2 * j + 1], hi, lo);
        *(uint4*)(base + 0 * SLABB + off) = hi;
        *(uint4*)(base + 1 * SLABB + off) = lo;
        split8(br[2 * j], br[2 * j + 1], hi, lo);
        *(uint4*)(base + 2 * SLABB + off) = hi;
        *(uint4*)(base + 3 * SLABB + off) = lo;
    }
}

__global__ void __launch_bounds__(256, 1)
bf16x3_gemm_nt(const float* __restrict__ A, const float* __restrict__ B,
               float* __restrict__ C, int lda, int ldb, int ldc,
               float alpha, int kchunks, int mode)
{
    extern __shared__ char smem[];
    const int tid  = threadIdx.x;
    const int wid  = tid >> 5;
    const int lane = tid & 31;
    const int row0 = blockIdx.y * 128;
    const int col0 = blockIdx.x * 128;

    if (mode == 1 && col0 > row0) return;
    const int nch = (mode == 2) ? 2 * (blockIdx.y + 1) : kchunks;

    const int wm = (wid >> 2) * 64;   // warp M offset (2 warps in M)
    const int wn = (wid & 3) * 32;    // warp N offset (4 warps in N)

    float acc[4][4][4];
#pragma unroll
    for (int i = 0; i < 4; i++)
#pragma unroll
        for (int j = 0; j < 4; j++)
#pragma unroll
            for (int r = 0; r < 4; r++) acc[i][j][r] = 0.f;

    const uint32_t sb = smem_u32(smem);

    float4 ar[8], br[8];
    ldg_chunk(A, B, lda, ldb, row0, col0, 0, tid, ar, br);
    sts_chunk(smem, 0, tid, ar, br);
    __syncthreads();

    for (int kt = 0; kt < nch; kt++) {
        const int st    = kt & 1;
        const bool pref = (kt + 1 < nch);
        if (pref) ldg_chunk(A, B, lda, ldb, row0, col0, kt + 1, tid, ar, br);

        const uint32_t sAh = sb + st * STAGEB;
        const uint32_t sAl = sAh + SLABB;
        const uint32_t sBh = sAh + 2 * SLABB;
        const uint32_t sBl = sAh + 3 * SLABB;

#pragma unroll
        for (int ks = 0; ks < 4; ks++) {
            uint32_t bh[4][2], bl[4][2];
#pragma unroll
            for (int nf = 0; nf < 4; nf++) {
                const uint32_t roff = SWZ128((uint32_t)(
                    (wn + nf * 8 + (lane & 7)) * 128 +
                    (ks * 2 + ((lane >> 3) & 1)) * 16));
                ldm_x2(bh[nf], sBh + roff);
                ldm_x2(bl[nf], sBl + roff);
            }
#pragma unroll
            for (int mf = 0; mf < 4; mf++) {
                const uint32_t aoff = SWZ128((uint32_t)(
                    (wm + mf * 16 + (lane & 15)) * 128 +
                    (ks * 2 + (lane >> 4)) * 16));
                uint32_t ah[4], al[4];
                ldm_x4(ah, sAh + aoff);
                ldm_x4(al, sAl + aoff);
#pragma unroll
                for (int nf = 0; nf < 4; nf++) {
                    mma_bf16(acc[mf][nf], ah, bh[nf]);   // hi*hi
                    mma_bf16(acc[mf][nf], al, bh[nf]);   // lo*hi
                    mma_bf16(acc[mf][nf], ah, bl[nf]);   // hi*lo
                }
            }
        }
        __syncthreads();
        if (pref) sts_chunk(smem, st ^ 1, tid, ar, br);
        __syncthreads();
    }

    // epilogue: m16n8 C fragment -> gmem, scaled
    const int r0 = lane >> 2;
    const int c0 = (lane & 3) * 2;
#pragma unroll
    for (int mf = 0; mf < 4; mf++) {
#pragma unroll
        for (int nf = 0; nf < 4; nf++) {
            const int row = row0 + wm + mf * 16 + r0;
            const int col = col0 + wn + nf * 8 + c0;
            float2 v0 = make_float2(acc[mf][nf][0] * alpha,
                                    acc[mf][nf][1] * alpha);
            float2 v1 = make_float2(acc[mf][nf][2] * alpha,
                                    acc[mf][nf][3] * alpha);
            *(float2*)(C + (size_t)row * ldc + col)       = v0;
            *(float2*)(C + (size_t)(row + 8) * ldc + col) = v1;
        }
    }
}

// ---------------------------------------------------------------------------
// 32x32 tiled transpose: out[c*R + r] = in[r*C + c]
// ---------------------------------------------------------------------------
__global__ void transpose_k(const float* __restrict__ in, float* __restrict__ out,
                            int R, int C)
{
    __shared__ float t[32][33];
    const int bx = blockIdx.x * 32;
    const int by = blockIdx.y * 32;
    const int tx = threadIdx.x;
    for (int j = threadIdx.y; j < 32; j += 8)
        t[j][tx] = in[(size_t)(by + j) * C + bx + tx];
    __syncthreads();
    for (int j = threadIdx.y; j < 32; j += 8)
        out[(size_t)(bx + j) * R + by + tx] = t[tx][j];
}

// ---------------------------------------------------------------------------
// causal row softmax (scores pre-scaled); zero-pads row to 128-block boundary
// ---------------------------------------------------------------------------
__global__ void softmax_rows(float* __restrict__ S)
{
    __shared__ float red[256];
    const int row = blockIdx.x;
    const int tid = threadIdx.x;
    float* srow = S + (size_t)row * NSEQ;
    const int n      = row + 1;
    const int padded = (row & ~127) + 128;

    float m = -1e30f;
    for (int c = tid; c < n; c += 256) m = fmaxf(m, srow[c]);
    red[tid] = m;
    __syncthreads();
    for (int s = 128; s > 0; s >>= 1) {
        if (tid < s) red[tid] = fmaxf(red[tid], red[tid + s]);
        __syncthreads();
    }
    m = red[0];
    __syncthreads();

    float sum = 0.f;
    for (int c = tid; c < n; c += 256) sum += __expf(srow[c] - m);
    red[tid] = sum;
    __syncthreads();
    for (int s = 128; s > 0; s >>= 1) {
        if (tid < s) red[tid] += red[tid + s];
        __syncthreads();
    }
    const float inv = 1.0f / red[0];

    for (int c = tid; c < n; c += 256) srow[c] = __expf(srow[c] - m) * inv;
    for (int c = n + tid; c < padded; c += 256) srow[c] = 0.f;
}

// ---------------------------------------------------------------------------
extern "C" void kernel_launch(void* const* d_in, const int* in_sizes, int n_in,
                              void* d_out, int out_size)
{
    const float* q  = (const float*)d_in[0];
    const float* k  = (const float*)d_in[1];
    const float* v  = (const float*)d_in[2];
    const float* Wq = (const float*)d_in[3];
    const float* Wk = (const float*)d_in[4];
    const float* Wv = (const float*)d_in[5];
    float* out = (float*)d_out;

    float *Q, *K, *V, *VT, *WT, *S;
    cudaGetSymbolAddress((void**)&Q,  g_Q);
    cudaGetSymbolAddress((void**)&K,  g_K);
    cudaGetSymbolAddress((void**)&V,  g_V);
    cudaGetSymbolAddress((void**)&VT, g_VT);
    cudaGetSymbolAddress((void**)&WT, g_WT);
    cudaGetSymbolAddress((void**)&S,  g_S);
    float* WqT = WT;
    float* WkT = WT + (size_t)DIM * DIM;
    float* WvT = WT + 2 * (size_t)DIM * DIM;

    cudaFuncSetAttribute(bf16x3_gemm_nt,
                         cudaFuncAttributeMaxDynamicSharedMemorySize,
                         SMEM_GEMM_BYTES);

    const dim3 blk(256);
    const dim3 tblk(32, 8);

    // weight transposes: W^T is the [N,K] K-major operand for the NT GEMM
    transpose_k<<<dim3(DIM / 32, DIM / 32), tblk>>>(Wq, WqT, DIM, DIM);
    transpose_k<<<dim3(DIM / 32, DIM / 32), tblk>>>(Wk, WkT, DIM, DIM);
    transpose_k<<<dim3(DIM / 32, DIM / 32), tblk>>>(Wv, WvT, DIM, DIM);

    // projections
    const dim3 gproj(DIM / 128, NSEQ / 128);
    bf16x3_gemm_nt<<<gproj, blk, SMEM_GEMM_BYTES>>>(q, WqT, Q, DIM, DIM, DIM,
                                                    1.0f, DIM / BKF, 0);
    bf16x3_gemm_nt<<<gproj, blk, SMEM_GEMM_BYTES>>>(k, WkT, K, DIM, DIM, DIM,
                                                    1.0f, DIM / BKF, 0);
    bf16x3_gemm_nt<<<gproj, blk, SMEM_GEMM_BYTES>>>(v, WvT, V, DIM, DIM, DIM,
                                                    1.0f, DIM / BKF, 0);

    // V^T for the P@V NT GEMM
    transpose_k<<<dim3(DIM / 32, NSEQ / 32), tblk>>>(V, VT, NSEQ, DIM);

    // scores: S = (Q K^T) / sqrt(Dk), lower-triangular tiles only
    const dim3 gsc(NSEQ / 128, NSEQ / 128);
    bf16x3_gemm_nt<<<gsc, blk, SMEM_GEMM_BYTES>>>(Q, K, S, DIM, DIM, NSEQ,
                                                  0.03125f, DIM / BKF, 1);

    softmax_rows<<<NSEQ, blk>>>(S);

    // O = P @ V = P @ (V^T)^T, causal k-limit per block row
    bf16x3_gemm_nt<<<gproj, blk, SMEM_GEMM_BYTES>>>(S, VT, out, NSEQ, NSEQ, DIM,
                                                    1.0f, NSEQ / BKF, 2);
}

// round 4
// speedup vs baseline: 3.0031x; 2.0288x over previous
#include <cuda_runtime.h>
#include <cuda_bf16.h>
#include <cstdint>

#define NSEQ 8192
#define DIM  1024

// ---------------- scratch (module statics; no runtime allocation) ----------
__device__ __nv_bfloat16 g_qh[(size_t)NSEQ * DIM], g_ql[(size_t)NSEQ * DIM];
__device__ __nv_bfloat16 g_kh[(size_t)NSEQ * DIM], g_kl[(size_t)NSEQ * DIM];
__device__ __nv_bfloat16 g_vh[(size_t)NSEQ * DIM], g_vl[(size_t)NSEQ * DIM];
__device__ __nv_bfloat16 g_WTh[3][(size_t)DIM * DIM], g_WTl[3][(size_t)DIM * DIM];
__device__ __nv_bfloat16 g_Qh[(size_t)NSEQ * DIM], g_Ql[(size_t)NSEQ * DIM];
__device__ __nv_bfloat16 g_Kh[(size_t)NSEQ * DIM], g_Kl[(size_t)NSEQ * DIM];
__device__ float         g_V [(size_t)NSEQ * DIM];
__device__ __nv_bfloat16 g_VTh[(size_t)DIM * NSEQ], g_VTl[(size_t)DIM * NSEQ];
__device__ float         g_S [(size_t)NSEQ * NSEQ];
__device__ __nv_bfloat16 g_Ph[(size_t)NSEQ * NSEQ], g_Pl[(size_t)NSEQ * NSEQ];

// ---------------- helpers ---------------------------------------------------
__device__ __forceinline__ uint32_t smem_u32(const void* p) {
    uint32_t a;
    asm("{ .reg .u64 t; cvta.to.shared.u64 t, %1; cvt.u32.u64 %0, t; }"
        : "=r"(a) : "l"(p));
    return a;
}
#define SWZ128(off) ((off) ^ (((off) >> 3) & 0x70))

__device__ __forceinline__ void ldm_x4(uint32_t* r, uint32_t addr) {
    asm volatile("ldmatrix.sync.aligned.m8n8.x4.shared.b16 {%0,%1,%2,%3}, [%4];"
                 : "=r"(r[0]), "=r"(r[1]), "=r"(r[2]), "=r"(r[3]) : "r"(addr));
}
__device__ __forceinline__ void mma_bf16(float* c, const uint32_t* a,
                                         const uint32_t* b) {
    asm volatile(
        "mma.sync.aligned.m16n8k16.row.col.f32.bf16.bf16.f32 "
        "{%0,%1,%2,%3}, {%4,%5,%6,%7}, {%8,%9}, {%0,%1,%2,%3};"
        : "+f"(c[0]), "+f"(c[1]), "+f"(c[2]), "+f"(c[3])
        : "r"(a[0]), "r"(a[1]), "r"(a[2]), "r"(a[3]), "r"(b[0]), "r"(b[1]));
}
__device__ __forceinline__ void cpa16(uint32_t dst, const void* src) {
    asm volatile("cp.async.cg.shared.global [%0], [%1], 16;"
                 :: "r"(dst), "l"(src));
}
#define CPA_COMMIT() asm volatile("cp.async.commit_group;" ::: "memory")
#define CPA_WAIT1()  asm volatile("cp.async.wait_group 1;" ::: "memory")

__device__ __forceinline__ uint16_t bf16bits(__nv_bfloat16 h) {
    return *reinterpret_cast<uint16_t*>(&h);
}
__device__ __forceinline__ void split1(float x, __nv_bfloat16& h, __nv_bfloat16& l) {
    h = __float2bfloat16_rn(x);
    l = __float2bfloat16_rn(x - __bfloat162float(h));
}

// ---------------------------------------------------------------------------
// bf16x3 NT GEMM on pre-split operands.
// C[M,N] = alpha * A[M,K] @ B[N,K]^T, A/B given as (hi,lo) bf16 K-major.
// CTA tile 256x128, warp tile 64x64 (8 warps: 4 in M, 2 in N), BK=64,
// 2-stage cp.async pipeline.
// cmode: 0 plain; 1 causal tile skip (scores); 2 causal k-limit (P@V).
// osplit: 0 -> C fp32; 1 -> write (Chi,Clo) bf16 split.
// ---------------------------------------------------------------------------
#define BM 256
#define BN 128
#define BK 64
#define SLAB_A (BM * BK * 2)          // 32 KB
#define SLAB_B (BN * BK * 2)          // 16 KB
#define STAGEB (2 * SLAB_A + 2 * SLAB_B)  // 96 KB
#define SMEM_GEMM_BYTES (2 * STAGEB)      // 192 KB

__device__ __forceinline__ void issue_chunk(
    uint32_t sstage,
    const __nv_bfloat16* __restrict__ Ah, const __nv_bfloat16* __restrict__ Al,
    const __nv_bfloat16* __restrict__ Bh, const __nv_bfloat16* __restrict__ Bl,
    int lda, int ldb, int row0, int col0, int kt, int tid)
{
#pragma unroll
    for (int i = 0; i < 8; i++) {          // A: 2048 16B chunks per slab
        const int idx = i * 256 + tid;
        const int row = idx >> 3, c = idx & 7;
        const uint32_t off = SWZ128((uint32_t)(row * 128 + c * 16));
        const size_t g = (size_t)(row0 + row) * lda + (size_t)kt * BK + c * 8;
        cpa16(sstage + off, Ah + g);
        cpa16(sstage + SLAB_A + off, Al + g);
    }
#pragma unroll
    for (int i = 0; i < 4; i++) {          // B: 1024 16B chunks per slab
        const int idx = i * 256 + tid;
        const int row = idx >> 3, c = idx & 7;
        const uint32_t off = SWZ128((uint32_t)(row * 128 + c * 16));
        const size_t g = (size_t)(col0 + row) * ldb + (size_t)kt * BK + c * 8;
        cpa16(sstage + 2 * SLAB_A + off, Bh + g);
        cpa16(sstage + 2 * SLAB_A + SLAB_B + off, Bl + g);
    }
}

__global__ void __launch_bounds__(256)
gemm_nt(const __nv_bfloat16* __restrict__ Ah, const __nv_bfloat16* __restrict__ Al,
        const __nv_bfloat16* __restrict__ Bh, const __nv_bfloat16* __restrict__ Bl,
        float* __restrict__ C,
        __nv_bfloat16* __restrict__ Chi, __nv_bfloat16* __restrict__ Clo,
        int lda, int ldb, int ldc, float alpha, int kchunks,
        int cmode, int osplit)
{
    extern __shared__ char smem[];
    const int tid  = threadIdx.x;
    const int wid  = tid >> 5;
    const int lane = tid & 31;
    const int row0 = blockIdx.y * BM;
    const int col0 = blockIdx.x * BN;

    if (cmode == 1 && col0 >= row0 + BM) return;
    const int nch = (cmode == 2) ? 4 * (blockIdx.y + 1) : kchunks;

    const int wm = (wid & 3) * 64;
    const int wn = (wid >> 2) * 64;

    float acc[4][8][4];
#pragma unroll
    for (int i = 0; i < 4; i++)
#pragma unroll
        for (int j = 0; j < 8; j++)
#pragma unroll
            for (int r = 0; r < 4; r++) acc[i][j][r] = 0.f;

    const uint32_t sb = smem_u32(smem);

    issue_chunk(sb, Ah, Al, Bh, Bl, lda, ldb, row0, col0, 0, tid);
    CPA_COMMIT();
    issue_chunk(sb + STAGEB, Ah, Al, Bh, Bl, lda, ldb, row0, col0, 1, tid);
    CPA_COMMIT();

    for (int kt = 0; kt < nch; kt++) {
        const int st = kt & 1;
        CPA_WAIT1();
        __syncthreads();

        const uint32_t sAh = sb + st * STAGEB;
        const uint32_t sAl = sAh + SLAB_A;
        const uint32_t sBh = sAh + 2 * SLAB_A;
        const uint32_t sBl = sBh + SLAB_B;

#pragma unroll
        for (int ks = 0; ks < 4; ks++) {
            uint32_t bh[4][4], bl[4][4];
#pragma unroll
            for (int np = 0; np < 4; np++) {
                const uint32_t roff = SWZ128((uint32_t)(
                    (wn + np * 16 + ((lane >> 4) << 3) + (lane & 7)) * 128 +
                    ks * 32 + ((lane >> 3) & 1) * 16));
                ldm_x4(bh[np], sBh + roff);
                ldm_x4(bl[np], sBl + roff);
            }
#pragma unroll
            for (int mf = 0; mf < 4; mf++) {
                const uint32_t aoff = SWZ128((uint32_t)(
                    (wm + mf * 16 + (lane & 15)) * 128 +
                    ks * 32 + ((lane >> 4) & 1) * 16));
                uint32_t ah[4], al[4];
                ldm_x4(ah, sAh + aoff);
                ldm_x4(al, sAl + aoff);
#pragma unroll
                for (int np = 0; np < 4; np++) {
                    mma_bf16(acc[mf][2 * np], ah, &bh[np][0]);
                    mma_bf16(acc[mf][2 * np], al, &bh[np][0]);
                    mma_bf16(acc[mf][2 * np], ah, &bl[np][0]);
                    mma_bf16(acc[mf][2 * np + 1], ah, &bh[np][2]);
                    mma_bf16(acc[mf][2 * np + 1], al, &bh[np][2]);
                    mma_bf16(acc[mf][2 * np + 1], ah, &bl[np][2]);
                }
            }
        }
        __syncthreads();
        if (kt + 2 < nch)
            issue_chunk(sb + st * STAGEB, Ah, Al, Bh, Bl, lda, ldb,
                        row0, col0, kt + 2, tid);
        CPA_COMMIT();
    }

    // epilogue
    const int r0 = lane >> 2;
    const int c0 = (lane & 3) * 2;
#pragma unroll
    for (int mf = 0; mf < 4; mf++) {
#pragma unroll
        for (int nf = 0; nf < 8; nf++) {
            const int row = row0 + wm + mf * 16 + r0;
            const int col = col0 + wn + nf * 8 + c0;
            const float x0 = acc[mf][nf][0] * alpha;
            const float x1 = acc[mf][nf][1] * alpha;
            const float x2 = acc[mf][nf][2] * alpha;
            const float x3 = acc[mf][nf][3] * alpha;
            if (!osplit) {
                *(float2*)(C + (size_t)row * ldc + col)       = make_float2(x0, x1);
                *(float2*)(C + (size_t)(row + 8) * ldc + col) = make_float2(x2, x3);
            } else {
                __nv_bfloat16 h0, l0, h1, l1;
                split1(x0, h0, l0); split1(x1, h1, l1);
                *(uint32_t*)(Chi + (size_t)row * ldc + col) =
                    (uint32_t)bf16bits(h0) | ((uint32_t)bf16bits(h1) << 16);
                *(uint32_t*)(Clo + (size_t)row * ldc + col) =
                    (uint32_t)bf16bits(l0) | ((uint32_t)bf16bits(l1) << 16);
                split1(x2, h0, l0); split1(x3, h1, l1);
                *(uint32_t*)(Chi + (size_t)(row + 8) * ldc + col) =
                    (uint32_t)bf16bits(h0) | ((uint32_t)bf16bits(h1) << 16);
                *(uint32_t*)(Clo + (size_t)(row + 8) * ldc + col) =
                    (uint32_t)bf16bits(l0) | ((uint32_t)bf16bits(l1) << 16);
            }
        }
    }
}

// ---------------------------------------------------------------------------
// elementwise fp32 -> (hi,lo) bf16 split
// ---------------------------------------------------------------------------
__global__ void split_f32(const float* __restrict__ in,
                          __nv_bfloat16* __restrict__ hi,
                          __nv_bfloat16* __restrict__ lo, size_t n4)
{
    const size_t i = (size_t)blockIdx.x * blockDim.x + threadIdx.x;
    if (i >= n4) return;
    const float4 v = ((const float4*)in)[i];
    __nv_bfloat16 h0, l0, h1, l1, h2, l2, h3, l3;
    split1(v.x, h0, l0); split1(v.y, h1, l1);
    split1(v.z, h2, l2); split1(v.w, h3, l3);
    uint2 H, L;
    H.x = (uint32_t)bf16bits(h0) | ((uint32_t)bf16bits(h1) << 16);
    H.y = (uint32_t)bf16bits(h2) | ((uint32_t)bf16bits(h3) << 16);
    L.x = (uint32_t)bf16bits(l0) | ((uint32_t)bf16bits(l1) << 16);
    L.y = (uint32_t)bf16bits(l2) | ((uint32_t)bf16bits(l3) << 16);
    ((uint2*)hi)[i] = H;
    ((uint2*)lo)[i] = L;
}

// ---------------------------------------------------------------------------
// transpose + split: in fp32 [R][C] -> outhi/outlo bf16 [C][R]
// ---------------------------------------------------------------------------
__global__ void transpose_split(const float* __restrict__ in,
                                __nv_bfloat16* __restrict__ outhi,
                                __nv_bfloat16* __restrict__ outlo, int R, int C)
{
    __shared__ float t[32][33];
    const int bx = blockIdx.x * 32;   // col tile
    const int by = blockIdx.y * 32;   // row tile
    const int tx = threadIdx.x;
    for (int j = threadIdx.y; j < 32; j += 8)
        t[j][tx] = in[(size_t)(by + j) * C + bx + tx];
    __syncthreads();
    for (int j = threadIdx.y; j < 32; j += 8) {
        const float x = t[tx][j];
        __nv_bfloat16 h, l;
        split1(x, h, l);
        outhi[(size_t)(bx + j) * R + by + tx] = h;
        outlo[(size_t)(bx + j) * R + by + tx] = l;
    }
}

// ---------------------------------------------------------------------------
// causal row softmax on fp32 S; writes split bf16 P; zero-pads to 256-boundary
// ---------------------------------------------------------------------------
__global__ void softmax_split(const float* __restrict__ S,
                              __nv_bfloat16* __restrict__ Ph,
                              __nv_bfloat16* __restrict__ Pl)
{
    __shared__ float red[256];
    const int row = blockIdx.x;
    const int tid = threadIdx.x;
    const float* srow = S + (size_t)row * NSEQ;
    __nv_bfloat16* ph = Ph + (size_t)row * NSEQ;
    __nv_bfloat16* pl = Pl + (size_t)row * NSEQ;
    const int n      = row + 1;
    const int padded = (row & ~255) + 256;

    float m = -1e30f;
    for (int c = tid; c < n; c += 256) m = fmaxf(m, srow[c]);
    red[tid] = m;
    __syncthreads();
    for (int s = 128; s > 0; s >>= 1) {
        if (tid < s) red[tid] = fmaxf(red[tid], red[tid + s]);
        __syncthreads();
    }
    m = red[0];
    __syncthreads();

    float sum = 0.f;
    for (int c = tid; c < n; c += 256) sum += __expf(srow[c] - m);
    red[tid] = sum;
    __syncthreads();
    for (int s = 128; s > 0; s >>= 1) {
        if (tid < s) red[tid] += red[tid + s];
        __syncthreads();
    }
    const float inv = 1.0f / red[0];

    const __nv_bfloat16 z = __float2bfloat16(0.f);
    for (int c = tid; c < n; c += 256) {
        const float p = __expf(srow[c] - m) * inv;
        __nv_bfloat16 h, l;
        split1(p, h, l);
        ph[c] = h; pl[c] = l;
    }
    for (int c = n + tid; c < padded; c += 256) { ph[c] = z; pl[c] = z; }
}

// ---------------------------------------------------------------------------
extern "C" void kernel_launch(void* const* d_in, const int* in_sizes, int n_in,
                              void* d_out, int out_size)
{
    const float* q  = (const float*)d_in[0];
    const float* k  = (const float*)d_in[1];
    const float* v  = (const float*)d_in[2];
    const float* Wq = (const float*)d_in[3];
    const float* Wk = (const float*)d_in[4];
    const float* Wv = (const float*)d_in[5];
    float* out = (float*)d_out;

    __nv_bfloat16 *qh, *ql, *kh, *kl, *vh, *vl, *WTh, *WTl;
    __nv_bfloat16 *Qh, *Ql, *Kh, *Kl, *VTh, *VTl, *Ph, *Pl;
    float *V, *S;
    cudaGetSymbolAddress((void**)&qh, g_qh);  cudaGetSymbolAddress((void**)&ql, g_ql);
    cudaGetSymbolAddress((void**)&kh, g_kh);  cudaGetSymbolAddress((void**)&kl, g_kl);
    cudaGetSymbolAddress((void**)&vh, g_vh);  cudaGetSymbolAddress((void**)&vl, g_vl);
    cudaGetSymbolAddress((void**)&WTh, g_WTh); cudaGetSymbolAddress((void**)&WTl, g_WTl);
    cudaGetSymbolAddress((void**)&Qh, g_Qh);  cudaGetSymbolAddress((void**)&Ql, g_Ql);
    cudaGetSymbolAddress((void**)&Kh, g_Kh);  cudaGetSymbolAddress((void**)&Kl, g_Kl);
    cudaGetSymbolAddress((void**)&V,  g_V);
    cudaGetSymbolAddress((void**)&VTh, g_VTh); cudaGetSymbolAddress((void**)&VTl, g_VTl);
    cudaGetSymbolAddress((void**)&S,  g_S);
    cudaGetSymbolAddress((void**)&Ph, g_Ph);  cudaGetSymbolAddress((void**)&Pl, g_Pl);

    const size_t WW = (size_t)DIM * DIM;

    cudaFuncSetAttribute(gemm_nt, cudaFuncAttributeMaxDynamicSharedMemorySize,
                         SMEM_GEMM_BYTES);

    const dim3 blk(256);
    const dim3 tblk(32, 8);

    // input splits
    const size_t n4 = (size_t)NSEQ * DIM / 4;
    split_f32<<<(unsigned)((n4 + 255) / 256), blk>>>(q, qh, ql, n4);
    split_f32<<<(unsigned)((n4 + 255) / 256), blk>>>(k, kh, kl, n4);
    split_f32<<<(unsigned)((n4 + 255) / 256), blk>>>(v, vh, vl, n4);

    // weight transpose+split
    transpose_split<<<dim3(DIM / 32, DIM / 32), tblk>>>(Wq, WTh, WTl, DIM, DIM);
    transpose_split<<<dim3(DIM / 32, DIM / 32), tblk>>>(Wk, WTh + WW, WTl + WW, DIM, DIM);
    transpose_split<<<dim3(DIM / 32, DIM / 32), tblk>>>(Wv, WTh + 2 * WW, WTl + 2 * WW, DIM, DIM);

    // projections (Q,K written split; V fp32 for transpose)
    const dim3 gproj(DIM / BN, NSEQ / BM);           // (8, 32)
    gemm_nt<<<gproj, blk, SMEM_GEMM_BYTES>>>(qh, ql, WTh, WTl,
        nullptr, Qh, Ql, DIM, DIM, DIM, 1.0f, DIM / BK, 0, 1);
    gemm_nt<<<gproj, blk, SMEM_GEMM_BYTES>>>(kh, kl, WTh + WW, WTl + WW,
        nullptr, Kh, Kl, DIM, DIM, DIM, 1.0f, DIM / BK, 0, 1);
    gemm_nt<<<gproj, blk, SMEM_GEMM_BYTES>>>(vh, vl, WTh + 2 * WW, WTl + 2 * WW,
        V, nullptr, nullptr, DIM, DIM, DIM, 1.0f, DIM / BK, 0, 0);

    // V^T split
    transpose_split<<<dim3(DIM / 32, NSEQ / 32), tblk>>>(V, VTh, VTl, NSEQ, DIM);

    // scores: S = (Q K^T)/sqrt(Dk), causal tile skip
    const dim3 gsc(NSEQ / BN, NSEQ / BM);            // (64, 32)
    gemm_nt<<<gsc, blk, SMEM_GEMM_BYTES>>>(Qh, Ql, Kh, Kl,
        S, nullptr, nullptr, DIM, DIM, NSEQ, 0.03125f, DIM / BK, 1, 0);

    // softmax -> split P (zero-padded to 256 granule)
    softmax_split<<<NSEQ, blk>>>(S, Ph, Pl);

    // O = P @ V^T^T, causal k-limit
    gemm_nt<<<gproj, blk, SMEM_GEMM_BYTES>>>(Ph, Pl, VTh, VTl,
        out, nullptr, nullptr, NSEQ, NSEQ, DIM, 1.0f, NSEQ / BK, 2, 0);
}

// round 5
// speedup vs baseline: 3.9607x; 1.3188x over previous
#include <cuda_runtime.h>
#include <cuda_fp16.h>
#include <cstdint>

#define NSEQ 8192
#define DIM  1024

// ---------------- scratch (module statics; no runtime allocation) ----------
__device__ __half g_qh[(size_t)NSEQ * DIM], g_ql[(size_t)NSEQ * DIM];
__device__ __half g_kh[(size_t)NSEQ * DIM], g_kl[(size_t)NSEQ * DIM];
__device__ __half g_vh[(size_t)NSEQ * DIM], g_vl[(size_t)NSEQ * DIM];
__device__ __half g_WT[3][(size_t)DIM * DIM];           // single fp16 (B operand)
__device__ __half g_Qh[(size_t)NSEQ * DIM], g_Ql[(size_t)NSEQ * DIM];
__device__ __half g_Kh[(size_t)NSEQ * DIM];             // single (B of scores)
__device__ __half g_Vr[(size_t)NSEQ * DIM];             // V row-major single
__device__ __half g_VT[(size_t)DIM * NSEQ];             // V^T single (B of PV)
__device__ float  g_S [(size_t)NSEQ * NSEQ];
__device__ __half g_Ph[(size_t)NSEQ * NSEQ], g_Pl[(size_t)NSEQ * NSEQ];

// ---------------- helpers ---------------------------------------------------
__device__ __forceinline__ uint32_t smem_u32(const void* p) {
    uint32_t a;
    asm("{ .reg .u64 t; cvta.to.shared.u64 t, %1; cvt.u32.u64 %0, t; }"
        : "=r"(a) : "l"(p));
    return a;
}
#define SWZ128(off) ((off) ^ (((off) >> 3) & 0x70))

__device__ __forceinline__ void ldm_x4(uint32_t* r, uint32_t addr) {
    asm volatile("ldmatrix.sync.aligned.m8n8.x4.shared.b16 {%0,%1,%2,%3}, [%4];"
                 : "=r"(r[0]), "=r"(r[1]), "=r"(r[2]), "=r"(r[3]) : "r"(addr));
}
__device__ __forceinline__ void mma_f16(float* c, const uint32_t* a,
                                        const uint32_t* b) {
    asm volatile(
        "mma.sync.aligned.m16n8k16.row.col.f32.f16.f16.f32 "
        "{%0,%1,%2,%3}, {%4,%5,%6,%7}, {%8,%9}, {%0,%1,%2,%3};"
        : "+f"(c[0]), "+f"(c[1]), "+f"(c[2]), "+f"(c[3])
        : "r"(a[0]), "r"(a[1]), "r"(a[2]), "r"(a[3]), "r"(b[0]), "r"(b[1]));
}
__device__ __forceinline__ void cpa16(uint32_t dst, const void* src) {
    asm volatile("cp.async.cg.shared.global [%0], [%1], 16;"
                 :: "r"(dst), "l"(src));
}
#define CPA_COMMIT() asm volatile("cp.async.commit_group;" ::: "memory")
#define CPA_WAIT1()  asm volatile("cp.async.wait_group 1;" ::: "memory")

__device__ __forceinline__ uint16_t h16(__half h) {
    return *reinterpret_cast<uint16_t*>(&h);
}
__device__ __forceinline__ void split1h(float x, __half& h, __half& l) {
    h = __float2half_rn(x);
    l = __float2half_rn(x - __half2float(h));
}

// ---------------------------------------------------------------------------
// fp16 2-term NT GEMM: C[M,N] = alpha * (Ah+Al)[M,K] @ Bh[N,K]^T
// A split (hi,lo) fp16, B single fp16, all K-major. CTA 256x128, warp 64x64,
// BK=64, 2-stage cp.async pipeline.
// cmode: 0 plain; 1 causal tile skip; 2 causal k-limit.
// omode: 0 -> C fp32; 1 -> (Chi,Clo) fp16 split; 2 -> Chi fp16 single.
// ---------------------------------------------------------------------------
#define BM 256
#define BN 128
#define BK 64
#define SLAB_A (BM * BK * 2)               // 32 KB
#define SLAB_B (BN * BK * 2)               // 16 KB
#define STAGEB (2 * SLAB_A + SLAB_B)       // 80 KB
#define SMEM_GEMM_BYTES (2 * STAGEB)       // 160 KB

__device__ __forceinline__ void issue_chunk(
    uint32_t sstage,
    const __half* __restrict__ Ah, const __half* __restrict__ Al,
    const __half* __restrict__ Bh,
    int lda, int ldb, int row0, int col0, int kt, int tid)
{
#pragma unroll
    for (int i = 0; i < 8; i++) {          // A: 2048 16B chunks per slab
        const int idx = i * 256 + tid;
        const int row = idx >> 3, c = idx & 7;
        const uint32_t off = SWZ128((uint32_t)(row * 128 + c * 16));
        const size_t g = (size_t)(row0 + row) * lda + (size_t)kt * BK + c * 8;
        cpa16(sstage + off, Ah + g);
        cpa16(sstage + SLAB_A + off, Al + g);
    }
#pragma unroll
    for (int i = 0; i < 4; i++) {          // B: 1024 16B chunks
        const int idx = i * 256 + tid;
        const int row = idx >> 3, c = idx & 7;
        const uint32_t off = SWZ128((uint32_t)(row * 128 + c * 16));
        const size_t g = (size_t)(col0 + row) * ldb + (size_t)kt * BK + c * 8;
        cpa16(sstage + 2 * SLAB_A + off, Bh + g);
    }
}

__global__ void __launch_bounds__(256)
gemm_nt(const __half* __restrict__ Ah, const __half* __restrict__ Al,
        const __half* __restrict__ Bh,
        float* __restrict__ C,
        __half* __restrict__ Chi, __half* __restrict__ Clo,
        int lda, int ldb, int ldc, float alpha, int kchunks,
        int cmode, int omode)
{
    extern __shared__ char smem[];
    const int tid  = threadIdx.x;
    const int wid  = tid >> 5;
    const int lane = tid & 31;
    const int row0 = blockIdx.y * BM;
    const int col0 = blockIdx.x * BN;

    if (cmode == 1 && col0 >= row0 + BM) return;
    const int nch = (cmode == 2) ? 4 * (blockIdx.y + 1) : kchunks;

    const int wm = (wid & 3) * 64;
    const int wn = (wid >> 2) * 64;

    float acc[4][8][4];
#pragma unroll
    for (int i = 0; i < 4; i++)
#pragma unroll
        for (int j = 0; j < 8; j++)
#pragma unroll
            for (int r = 0; r < 4; r++) acc[i][j][r] = 0.f;

    const uint32_t sb = smem_u32(smem);

    issue_chunk(sb, Ah, Al, Bh, lda, ldb, row0, col0, 0, tid);
    CPA_COMMIT();
    issue_chunk(sb + STAGEB, Ah, Al, Bh, lda, ldb, row0, col0, 1, tid);
    CPA_COMMIT();

    for (int kt = 0; kt < nch; kt++) {
        const int st = kt & 1;
        CPA_WAIT1();
        __syncthreads();

        const uint32_t sAh = sb + st * STAGEB;
        const uint32_t sAl = sAh + SLAB_A;
        const uint32_t sBh = sAh + 2 * SLAB_A;

#pragma unroll
        for (int ks = 0; ks < 4; ks++) {
            uint32_t bh[4][4];
#pragma unroll
            for (int np = 0; np < 4; np++) {
                const uint32_t roff = SWZ128((uint32_t)(
                    (wn + np * 16 + ((lane >> 4) << 3) + (lane & 7)) * 128 +
                    ks * 32 + ((lane >> 3) & 1) * 16));
                ldm_x4(bh[np], sBh + roff);
            }
#pragma unroll
            for (int mf = 0; mf < 4; mf++) {
                const uint32_t aoff = SWZ128((uint32_t)(
                    (wm + mf * 16 + (lane & 15)) * 128 +
                    ks * 32 + ((lane >> 4) & 1) * 16));
                uint32_t ah[4], al[4];
                ldm_x4(ah, sAh + aoff);
                ldm_x4(al, sAl + aoff);
#pragma unroll
                for (int np = 0; np < 4; np++) {
                    mma_f16(acc[mf][2 * np], ah, &bh[np][0]);
                    mma_f16(acc[mf][2 * np], al, &bh[np][0]);
                    mma_f16(acc[mf][2 * np + 1], ah, &bh[np][2]);
                    mma_f16(acc[mf][2 * np + 1], al, &bh[np][2]);
                }
            }
        }
        __syncthreads();
        if (kt + 2 < nch)
            issue_chunk(sb + st * STAGEB, Ah, Al, Bh, lda, ldb,
                        row0, col0, kt + 2, tid);
        CPA_COMMIT();
    }

    // epilogue
    const int r0 = lane >> 2;
    const int c0 = (lane & 3) * 2;
#pragma unroll
    for (int mf = 0; mf < 4; mf++) {
#pragma unroll
        for (int nf = 0; nf < 8; nf++) {
            const int row = row0 + wm + mf * 16 + r0;
            const int col = col0 + wn + nf * 8 + c0;
            const float x0 = acc[mf][nf][0] * alpha;
            const float x1 = acc[mf][nf][1] * alpha;
            const float x2 = acc[mf][nf][2] * alpha;
            const float x3 = acc[mf][nf][3] * alpha;
            if (omode == 0) {
                *(float2*)(C + (size_t)row * ldc + col)       = make_float2(x0, x1);
                *(float2*)(C + (size_t)(row + 8) * ldc + col) = make_float2(x2, x3);
            } else if (omode == 1) {
                __half h0, l0, h1, l1;
                split1h(x0, h0, l0); split1h(x1, h1, l1);
                *(uint32_t*)(Chi + (size_t)row * ldc + col) =
                    (uint32_t)h16(h0) | ((uint32_t)h16(h1) << 16);
                *(uint32_t*)(Clo + (size_t)row * ldc + col) =
                    (uint32_t)h16(l0) | ((uint32_t)h16(l1) << 16);
                split1h(x2, h0, l0); split1h(x3, h1, l1);
                *(uint32_t*)(Chi + (size_t)(row + 8) * ldc + col) =
                    (uint32_t)h16(h0) | ((uint32_t)h16(h1) << 16);
                *(uint32_t*)(Clo + (size_t)(row + 8) * ldc + col) =
                    (uint32_t)h16(l0) | ((uint32_t)h16(l1) << 16);
            } else {
                *(uint32_t*)(Chi + (size_t)row * ldc + col) =
                    (uint32_t)h16(__float2half_rn(x0)) |
                    ((uint32_t)h16(__float2half_rn(x1)) << 16);
                *(uint32_t*)(Chi + (size_t)(row + 8) * ldc + col) =
                    (uint32_t)h16(__float2half_rn(x2)) |
                    ((uint32_t)h16(__float2half_rn(x3)) << 16);
            }
        }
    }
}

// ---------------------------------------------------------------------------
// elementwise fp32 -> (hi,lo) fp16 split
// ---------------------------------------------------------------------------
__global__ void split_f32(const float* __restrict__ in,
                          __half* __restrict__ hi,
                          __half* __restrict__ lo, size_t n4)
{
    const size_t i = (size_t)blockIdx.x * blockDim.x + threadIdx.x;
    if (i >= n4) return;
    const float4 v = ((const float4*)in)[i];
    __half h0, l0, h1, l1, h2, l2, h3, l3;
    split1h(v.x, h0, l0); split1h(v.y, h1, l1);
    split1h(v.z, h2, l2); split1h(v.w, h3, l3);
    uint2 H, L;
    H.x = (uint32_t)h16(h0) | ((uint32_t)h16(h1) << 16);
    H.y = (uint32_t)h16(h2) | ((uint32_t)h16(h3) << 16);
    L.x = (uint32_t)h16(l0) | ((uint32_t)h16(l1) << 16);
    L.y = (uint32_t)h16(l2) | ((uint32_t)h16(l3) << 16);
    ((uint2*)hi)[i] = H;
    ((uint2*)lo)[i] = L;
}

// ---------------------------------------------------------------------------
// transpose fp32 -> fp16 single: out[c][r] = (half)in[r][c]
// ---------------------------------------------------------------------------
__global__ void transpose_f32_h(const float* __restrict__ in,
                                __half* __restrict__ out, int R, int C)
{
    __shared__ float t[32][33];
    const int bx = blockIdx.x * 32;
    const int by = blockIdx.y * 32;
    const int tx = threadIdx.x;
    for (int j = threadIdx.y; j < 32; j += 8)
        t[j][tx] = in[(size_t)(by + j) * C + bx + tx];
    __syncthreads();
    for (int j = threadIdx.y; j < 32; j += 8)
        out[(size_t)(bx + j) * R + by + tx] = __float2half_rn(t[tx][j]);
}

// ---------------------------------------------------------------------------
// transpose fp16 -> fp16: out[c][r] = in[r][c]
// ---------------------------------------------------------------------------
__global__ void transpose_h(const __half* __restrict__ in,
                            __half* __restrict__ out, int R, int C)
{
    __shared__ __half t[32][34];
    const int bx = blockIdx.x * 32;
    const int by = blockIdx.y * 32;
    const int tx = threadIdx.x;
    for (int j = threadIdx.y; j < 32; j += 8)
        t[j][tx] = in[(size_t)(by + j) * C + bx + tx];
    __syncthreads();
    for (int j = threadIdx.y; j < 32; j += 8)
        out[(size_t)(bx + j) * R + by + tx] = t[tx][j];
}

// ---------------------------------------------------------------------------
// causal row softmax on fp32 S; writes split fp16 P; zero-pads to 256-boundary
// ---------------------------------------------------------------------------
__global__ void softmax_split(const float* __restrict__ S,
                              __half* __restrict__ Ph,
                              __half* __restrict__ Pl)
{
    __shared__ float red[256];
    const int row = blockIdx.x;
    const int tid = threadIdx.x;
    const float* srow = S + (size_t)row * NSEQ;
    __half* ph = Ph + (size_t)row * NSEQ;
    __half* pl = Pl + (size_t)row * NSEQ;
    const int n      = row + 1;
    const int padded = (row & ~255) + 256;

    float m = -1e30f;
    for (int c = tid; c < n; c += 256) m = fmaxf(m, srow[c]);
    red[tid] = m;
    __syncthreads();
    for (int s = 128; s > 0; s >>= 1) {
        if (tid < s) red[tid] = fmaxf(red[tid], red[tid + s]);
        __syncthreads();
    }
    m = red[0];
    __syncthreads();

    float sum = 0.f;
    for (int c = tid; c < n; c += 256) sum += __expf(srow[c] - m);
    red[tid] = sum;
    __syncthreads();
    for (int s = 128; s > 0; s >>= 1) {
        if (tid < s) red[tid] += red[tid + s];
        __syncthreads();
    }
    const float inv = 1.0f / red[0];

    const __half z = __float2half(0.f);
    for (int c = tid; c < n; c += 256) {
        const float p = __expf(srow[c] - m) * inv;
        __half h, l;
        split1h(p, h, l);
        ph[c] = h; pl[c] = l;
    }
    for (int c = n + tid; c < padded; c += 256) { ph[c] = z; pl[c] = z; }
}

// ---------------------------------------------------------------------------
extern "C" void kernel_launch(void* const* d_in, const int* in_sizes, int n_in,
                              void* d_out, int out_size)
{
    const float* q  = (const float*)d_in[0];
    const float* k  = (const float*)d_in[1];
    const float* v  = (const float*)d_in[2];
    const float* Wq = (const float*)d_in[3];
    const float* Wk = (const float*)d_in[4];
    const float* Wv = (const float*)d_in[5];
    float* out = (float*)d_out;

    __half *qh, *ql, *kh, *kl, *vh, *vl, *WT;
    __half *Qh, *Ql, *Kh, *Vr, *VT, *Ph, *Pl;
    float *S;
    cudaGetSymbolAddress((void**)&qh, g_qh);  cudaGetSymbolAddress((void**)&ql, g_ql);
    cudaGetSymbolAddress((void**)&kh, g_kh);  cudaGetSymbolAddress((void**)&kl, g_kl);
    cudaGetSymbolAddress((void**)&vh, g_vh);  cudaGetSymbolAddress((void**)&vl, g_vl);
    cudaGetSymbolAddress((void**)&WT, g_WT);
    cudaGetSymbolAddress((void**)&Qh, g_Qh);  cudaGetSymbolAddress((void**)&Ql, g_Ql);
    cudaGetSymbolAddress((void**)&Kh, g_Kh);
    cudaGetSymbolAddress((void**)&Vr, g_Vr);  cudaGetSymbolAddress((void**)&VT, g_VT);
    cudaGetSymbolAddress((void**)&S,  g_S);
    cudaGetSymbolAddress((void**)&Ph, g_Ph);  cudaGetSymbolAddress((void**)&Pl, g_Pl);

    const size_t WW = (size_t)DIM * DIM;

    cudaFuncSetAttribute(gemm_nt, cudaFuncAttributeMaxDynamicSharedMemorySize,
                         SMEM_GEMM_BYTES);

    const dim3 blk(256);
    const dim3 tblk(32, 8);

    // input splits
    const size_t n4 = (size_t)NSEQ * DIM / 4;
    split_f32<<<(unsigned)((n4 + 255) / 256), blk>>>(q, qh, ql, n4);
    split_f32<<<(unsigned)((n4 + 255) / 256), blk>>>(k, kh, kl, n4);
    split_f32<<<(unsigned)((n4 + 255) / 256), blk>>>(v, vh, vl, n4);

    // weight transposes to single fp16
    transpose_f32_h<<<dim3(DIM / 32, DIM / 32), tblk>>>(Wq, WT, DIM, DIM);
    transpose_f32_h<<<dim3(DIM / 32, DIM / 32), tblk>>>(Wk, WT + WW, DIM, DIM);
    transpose_f32_h<<<dim3(DIM / 32, DIM / 32), tblk>>>(Wv, WT + 2 * WW, DIM, DIM);

    // projections: Q split (A of scores); K single (B of scores); V single row-major
    const dim3 gproj(DIM / BN, NSEQ / BM);           // (8, 32)
    gemm_nt<<<gproj, blk, SMEM_GEMM_BYTES>>>(qh, ql, WT,
        nullptr, Qh, Ql, DIM, DIM, DIM, 1.0f, DIM / BK, 0, 1);
    gemm_nt<<<gproj, blk, SMEM_GEMM_BYTES>>>(kh, kl, WT + WW,
        nullptr, Kh, nullptr, DIM, DIM, DIM, 1.0f, DIM / BK, 0, 2);
    gemm_nt<<<gproj, blk, SMEM_GEMM_BYTES>>>(vh, vl, WT + 2 * WW,
        nullptr, Vr, nullptr, DIM, DIM, DIM, 1.0f, DIM / BK, 0, 2);

    // V^T (fp16 -> fp16)
    transpose_h<<<dim3(DIM / 32, NSEQ / 32), tblk>>>(Vr, VT, NSEQ, DIM);

    // scores: S = (Q K^T)/sqrt(Dk), causal tile skip
    const dim3 gsc(NSEQ / BN, NSEQ / BM);            // (64, 32)
    gemm_nt<<<gsc, blk, SMEM_GEMM_BYTES>>>(Qh, Ql, Kh,
        S, nullptr, nullptr, DIM, DIM, NSEQ, 0.03125f, DIM / BK, 1, 0);

    // softmax -> split fp16 P (zero-padded to 256 granule)
    softmax_split<<<NSEQ, blk>>>(S, Ph, Pl);

    // O = P @ (V^T)^T, causal k-limit
    gemm_nt<<<gproj, blk, SMEM_GEMM_BYTES>>>(Ph, Pl, VT,
        out, nullptr, nullptr, NSEQ, NSEQ, DIM, 1.0f, NSEQ / BK, 2, 0);
}

// round 6
// speedup vs baseline: 5.5038x; 1.3896x over previous
#include <cuda_runtime.h>
#include <cuda_fp16.h>
#include <cstdint>

#define NSEQ 8192
#define DIM  1024

// ---------------- scratch (module statics; no runtime allocation) ----------
__device__ __half g_q16[(size_t)NSEQ * DIM];
__device__ __half g_k16[(size_t)NSEQ * DIM];
__device__ __half g_v16[(size_t)NSEQ * DIM];
__device__ __half g_WT[3][(size_t)DIM * DIM];          // W^T single fp16
__device__ __half g_Qh[(size_t)NSEQ * DIM], g_Ql[(size_t)NSEQ * DIM];
__device__ __half g_Kh[(size_t)NSEQ * DIM];
__device__ __half g_Vr[(size_t)NSEQ * DIM];
__device__ __half g_VT[(size_t)DIM * NSEQ];
__device__ float  g_S [(size_t)NSEQ * NSEQ];
__device__ __half g_P [(size_t)NSEQ * NSEQ];

// ---------------- helpers ---------------------------------------------------
__device__ __forceinline__ uint32_t smem_u32(const void* p) {
    uint32_t a;
    asm("{ .reg .u64 t; cvta.to.shared.u64 t, %1; cvt.u32.u64 %0, t; }"
        : "=r"(a) : "l"(p));
    return a;
}
#define SWZ128(off) ((off) ^ (((off) >> 3) & 0x70))

__device__ __forceinline__ void ldm_x4(uint32_t* r, uint32_t addr) {
    asm volatile("ldmatrix.sync.aligned.m8n8.x4.shared.b16 {%0,%1,%2,%3}, [%4];"
                 : "=r"(r[0]), "=r"(r[1]), "=r"(r[2]), "=r"(r[3]) : "r"(addr));
}
__device__ __forceinline__ void mma_f16(float* c, const uint32_t* a,
                                        const uint32_t* b) {
    asm volatile(
        "mma.sync.aligned.m16n8k16.row.col.f32.f16.f16.f32 "
        "{%0,%1,%2,%3}, {%4,%5,%6,%7}, {%8,%9}, {%0,%1,%2,%3};"
        : "+f"(c[0]), "+f"(c[1]), "+f"(c[2]), "+f"(c[3])
        : "r"(a[0]), "r"(a[1]), "r"(a[2]), "r"(a[3]), "r"(b[0]), "r"(b[1]));
}
__device__ __forceinline__ void cpa16(uint32_t dst, const void* src) {
    asm volatile("cp.async.cg.shared.global [%0], [%1], 16;"
                 :: "r"(dst), "l"(src));
}
#define CPA_COMMIT() asm volatile("cp.async.commit_group;" ::: "memory")
#define CPA_WAIT1()  asm volatile("cp.async.wait_group 1;" ::: "memory")

__device__ __forceinline__ uint16_t h16(__half h) {
    return *reinterpret_cast<uint16_t*>(&h);
}
__device__ __forceinline__ void split1h(float x, __half& h, __half& l) {
    h = __float2half_rn(x);
    l = __float2half_rn(x - __half2float(h));
}

// ---------------------------------------------------------------------------
// fp16 NT GEMM: C[M,N] = alpha * A[M,K] @ B[N,K]^T
// ASPLIT=1: A given as (hi,lo), 2 MMA terms; ASPLIT=0: single A, 1 term.
// CTA 256x128, warp 64x64, BK=64, 2-stage cp.async.
// cmode: 0 plain; 1 causal tile skip; 2 causal k-limit.
// omode: 0 -> C fp32; 1 -> (Chi,Clo) fp16 split; 2 -> Chi fp16 single.
// ---------------------------------------------------------------------------
#define BM 256
#define BN 128
#define BK 64
#define SLAB_A (BM * BK * 2)               // 32 KB
#define SLAB_B (BN * BK * 2)               // 16 KB
#define STAGE_BYTES(AS) (SLAB_A * (1 + (AS)) + SLAB_B)
#define SMEM_BYTES(AS)  (2 * STAGE_BYTES(AS))   // 96 KB / 160 KB

template <int ASPLIT>
__device__ __forceinline__ void issue_chunk(
    uint32_t sstage,
    const __half* __restrict__ Ah, const __half* __restrict__ Al,
    const __half* __restrict__ Bh,
    int lda, int ldb, int row0, int col0, int kt, int tid)
{
#pragma unroll
    for (int i = 0; i < 8; i++) {          // A: 2048 16B chunks per slab
        const int idx = i * 256 + tid;
        const int row = idx >> 3, c = idx & 7;
        const uint32_t off = SWZ128((uint32_t)(row * 128 + c * 16));
        const size_t g = (size_t)(row0 + row) * lda + (size_t)kt * BK + c * 8;
        cpa16(sstage + off, Ah + g);
        if (ASPLIT) cpa16(sstage + SLAB_A + off, Al + g);
    }
#pragma unroll
    for (int i = 0; i < 4; i++) {          // B: 1024 16B chunks
        const int idx = i * 256 + tid;
        const int row = idx >> 3, c = idx & 7;
        const uint32_t off = SWZ128((uint32_t)(row * 128 + c * 16));
        const size_t g = (size_t)(col0 + row) * ldb + (size_t)kt * BK + c * 8;
        cpa16(sstage + SLAB_A * (1 + ASPLIT) + off, Bh + g);
    }
}

template <int ASPLIT>
__global__ void __launch_bounds__(256)
gemm_nt(const __half* __restrict__ Ah, const __half* __restrict__ Al,
        const __half* __restrict__ Bh,
        float* __restrict__ C,
        __half* __restrict__ Chi, __half* __restrict__ Clo,
        int lda, int ldb, int ldc, float alpha, int kchunks,
        int cmode, int omode)
{
    extern __shared__ char smem[];
    const int tid  = threadIdx.x;
    const int wid  = tid >> 5;
    const int lane = tid & 31;
    const int row0 = blockIdx.y * BM;
    const int col0 = blockIdx.x * BN;

    if (cmode == 1 && col0 >= row0 + BM) return;
    const int nch = (cmode == 2) ? 4 * (blockIdx.y + 1) : kchunks;

    const int wm = (wid & 3) * 64;
    const int wn = (wid >> 2) * 64;

    float acc[4][8][4];
#pragma unroll
    for (int i = 0; i < 4; i++)
#pragma unroll
        for (int j = 0; j < 8; j++)
#pragma unroll
            for (int r = 0; r < 4; r++) acc[i][j][r] = 0.f;

    const uint32_t sb = smem_u32(smem);
    const uint32_t stageb = STAGE_BYTES(ASPLIT);

    issue_chunk<ASPLIT>(sb, Ah, Al, Bh, lda, ldb, row0, col0, 0, tid);
    CPA_COMMIT();
    issue_chunk<ASPLIT>(sb + stageb, Ah, Al, Bh, lda, ldb, row0, col0, 1, tid);
    CPA_COMMIT();

    for (int kt = 0; kt < nch; kt++) {
        const int st = kt & 1;
        CPA_WAIT1();
        __syncthreads();

        const uint32_t sAh = sb + st * stageb;
        const uint32_t sAl = sAh + SLAB_A;
        const uint32_t sBh = sAh + SLAB_A * (1 + ASPLIT);

#pragma unroll
        for (int ks = 0; ks < 4; ks++) {
            uint32_t bh[4][4];
#pragma unroll
            for (int np = 0; np < 4; np++) {
                const uint32_t roff = SWZ128((uint32_t)(
                    (wn + np * 16 + ((lane >> 4) << 3) + (lane & 7)) * 128 +
                    ks * 32 + ((lane >> 3) & 1) * 16));
                ldm_x4(bh[np], sBh + roff);
            }
#pragma unroll
            for (int mf = 0; mf < 4; mf++) {
                const uint32_t aoff = SWZ128((uint32_t)(
                    (wm + mf * 16 + (lane & 15)) * 128 +
                    ks * 32 + ((lane >> 4) & 1) * 16));
                uint32_t ah[4], al[4];
                ldm_x4(ah, sAh + aoff);
                if (ASPLIT) ldm_x4(al, sAl + aoff);
#pragma unroll
                for (int np = 0; np < 4; np++) {
                    mma_f16(acc[mf][2 * np], ah, &bh[np][0]);
                    if (ASPLIT) mma_f16(acc[mf][2 * np], al, &bh[np][0]);
                    mma_f16(acc[mf][2 * np + 1], ah, &bh[np][2]);
                    if (ASPLIT) mma_f16(acc[mf][2 * np + 1], al, &bh[np][2]);
                }
            }
        }
        __syncthreads();
        if (kt + 2 < nch)
            issue_chunk<ASPLIT>(sb + st * stageb, Ah, Al, Bh, lda, ldb,
                                row0, col0, kt + 2, tid);
        CPA_COMMIT();
    }

    // epilogue
    const int r0 = lane >> 2;
    const int c0 = (lane & 3) * 2;
#pragma unroll
    for (int mf = 0; mf < 4; mf++) {
#pragma unroll
        for (int nf = 0; nf < 8; nf++) {
            const int row = row0 + wm + mf * 16 + r0;
            const int col = col0 + wn + nf * 8 + c0;
            const float x0 = acc[mf][nf][0] * alpha;
            const float x1 = acc[mf][nf][1] * alpha;
            const float x2 = acc[mf][nf][2] * alpha;
            const float x3 = acc[mf][nf][3] * alpha;
            if (omode == 0) {
                *(float2*)(C + (size_t)row * ldc + col)       = make_float2(x0, x1);
                *(float2*)(C + (size_t)(row + 8) * ldc + col) = make_float2(x2, x3);
            } else if (omode == 1) {
                __half h0, l0, h1, l1;
                split1h(x0, h0, l0); split1h(x1, h1, l1);
                *(uint32_t*)(Chi + (size_t)row * ldc + col) =
                    (uint32_t)h16(h0) | ((uint32_t)h16(h1) << 16);
                *(uint32_t*)(Clo + (size_t)row * ldc + col) =
                    (uint32_t)h16(l0) | ((uint32_t)h16(l1) << 16);
                split1h(x2, h0, l0); split1h(x3, h1, l1);
                *(uint32_t*)(Chi + (size_t)(row + 8) * ldc + col) =
                    (uint32_t)h16(h0) | ((uint32_t)h16(h1) << 16);
                *(uint32_t*)(Clo + (size_t)(row + 8) * ldc + col) =
                    (uint32_t)h16(l0) | ((uint32_t)h16(l1) << 16);
            } else {
                *(uint32_t*)(Chi + (size_t)row * ldc + col) =
                    (uint32_t)h16(__float2half_rn(x0)) |
                    ((uint32_t)h16(__float2half_rn(x1)) << 16);
                *(uint32_t*)(Chi + (size_t)(row + 8) * ldc + col) =
                    (uint32_t)h16(__float2half_rn(x2)) |
                    ((uint32_t)h16(__float2half_rn(x3)) << 16);
            }
        }
    }
}

// ---------------------------------------------------------------------------
// fp32 -> fp16 single convert
// ---------------------------------------------------------------------------
__global__ void conv_f32_h(const float* __restrict__ in,
                           __half* __restrict__ out, size_t n4)
{
    const size_t i = (size_t)blockIdx.x * blockDim.x + threadIdx.x;
    if (i >= n4) return;
    const float4 v = ((const float4*)in)[i];
    uint2 H;
    H.x = (uint32_t)h16(__float2half_rn(v.x)) |
          ((uint32_t)h16(__float2half_rn(v.y)) << 16);
    H.y = (uint32_t)h16(__float2half_rn(v.z)) |
          ((uint32_t)h16(__float2half_rn(v.w)) << 16);
    ((uint2*)out)[i] = H;
}

// ---------------------------------------------------------------------------
// transpose fp32 -> fp16 single
// ---------------------------------------------------------------------------
__global__ void transpose_f32_h(const float* __restrict__ in,
                                __half* __restrict__ out, int R, int C)
{
    __shared__ float t[32][33];
    const int bx = blockIdx.x * 32;
    const int by = blockIdx.y * 32;
    const int tx = threadIdx.x;
    for (int j = threadIdx.y; j < 32; j += 8)
        t[j][tx] = in[(size_t)(by + j) * C + bx + tx];
    __syncthreads();
    for (int j = threadIdx.y; j < 32; j += 8)
        out[(size_t)(bx + j) * R + by + tx] = __float2half_rn(t[tx][j]);
}

// ---------------------------------------------------------------------------
// transpose fp16 -> fp16
// ---------------------------------------------------------------------------
__global__ void transpose_h(const __half* __restrict__ in,
                            __half* __restrict__ out, int R, int C)
{
    __shared__ __half t[32][34];
    const int bx = blockIdx.x * 32;
    const int by = blockIdx.y * 32;
    const int tx = threadIdx.x;
    for (int j = threadIdx.y; j < 32; j += 8)
        t[j][tx] = in[(size_t)(by + j) * C + bx + tx];
    __syncthreads();
    for (int j = threadIdx.y; j < 32; j += 8)
        out[(size_t)(bx + j) * R + by + tx] = t[tx][j];
}

// ---------------------------------------------------------------------------
// single-pass causal row softmax: S fp32 row held in registers (256thr x 32),
// write fp16 P, zero-pad to 256-boundary.
// ---------------------------------------------------------------------------
__global__ void __launch_bounds__(256)
softmax1(const float* __restrict__ S, __half* __restrict__ P)
{
    __shared__ float red[8];
    const int row = blockIdx.x;
    const int tid = threadIdx.x;
    const int lane = tid & 31;
    const int wid = tid >> 5;
    const float* srow = S + (size_t)row * NSEQ;
    __half* prow = P + (size_t)row * NSEQ;
    const int n      = row + 1;
    const int padded = (row & ~255) + 256;

    float v[32];
    float m = -1e30f;
#pragma unroll
    for (int i = 0; i < 32; i++) {
        const int c = i * 256 + tid;
        v[i] = (c < n) ? srow[c] : -1e30f;
        m = fmaxf(m, v[i]);
    }
#pragma unroll
    for (int o = 16; o; o >>= 1) m = fmaxf(m, __shfl_xor_sync(~0u, m, o));
    if (lane == 0) red[wid] = m;
    __syncthreads();
    m = -1e30f;
#pragma unroll
    for (int w = 0; w < 8; w++) m = fmaxf(m, red[w]);
    __syncthreads();

    float sum = 0.f;
#pragma unroll
    for (int i = 0; i < 32; i++) {
        const float e = __expf(v[i] - m);   // -1e30 - m -> exp = 0
        v[i] = e;
        sum += e;
    }
#pragma unroll
    for (int o = 16; o; o >>= 1) sum += __shfl_xor_sync(~0u, sum, o);
    if (lane == 0) red[wid] = sum;
    __syncthreads();
    sum = 0.f;
#pragma unroll
    for (int w = 0; w < 8; w++) sum += red[w];
    const float inv = 1.0f / sum;

#pragma unroll
    for (int i = 0; i < 32; i++) {
        const int c = i * 256 + tid;
        if (c < padded) prow[c] = __float2half_rn(v[i] * inv);
    }
}

// ---------------------------------------------------------------------------
extern "C" void kernel_launch(void* const* d_in, const int* in_sizes, int n_in,
                              void* d_out, int out_size)
{
    const float* q  = (const float*)d_in[0];
    const float* k  = (const float*)d_in[1];
    const float* v  = (const float*)d_in[2];
    const float* Wq = (const float*)d_in[3];
    const float* Wk = (const float*)d_in[4];
    const float* Wv = (const float*)d_in[5];
    float* out = (float*)d_out;

    __half *q16, *k16, *v16, *WT, *Qh, *Ql, *Kh, *Vr, *VT, *P;
    float *S;
    cudaGetSymbolAddress((void**)&q16, g_q16);
    cudaGetSymbolAddress((void**)&k16, g_k16);
    cudaGetSymbolAddress((void**)&v16, g_v16);
    cudaGetSymbolAddress((void**)&WT, g_WT);
    cudaGetSymbolAddress((void**)&Qh, g_Qh);  cudaGetSymbolAddress((void**)&Ql, g_Ql);
    cudaGetSymbolAddress((void**)&Kh, g_Kh);
    cudaGetSymbolAddress((void**)&Vr, g_Vr);  cudaGetSymbolAddress((void**)&VT, g_VT);
    cudaGetSymbolAddress((void**)&S,  g_S);
    cudaGetSymbolAddress((void**)&P,  g_P);

    const size_t WW = (size_t)DIM * DIM;

    cudaFuncSetAttribute(gemm_nt<0>, cudaFuncAttributeMaxDynamicSharedMemorySize,
                         SMEM_BYTES(0));
    cudaFuncSetAttribute(gemm_nt<1>, cudaFuncAttributeMaxDynamicSharedMemorySize,
                         SMEM_BYTES(1));

    const dim3 blk(256);
    const dim3 tblk(32, 8);

    // input converts (single fp16)
    const size_t n4 = (size_t)NSEQ * DIM / 4;
    conv_f32_h<<<(unsigned)((n4 + 255) / 256), blk>>>(q, q16, n4);
    conv_f32_h<<<(unsigned)((n4 + 255) / 256), blk>>>(k, k16, n4);
    conv_f32_h<<<(unsigned)((n4 + 255) / 256), blk>>>(v, v16, n4);

    // weight transposes to single fp16
    transpose_f32_h<<<dim3(DIM / 32, DIM / 32), tblk>>>(Wq, WT, DIM, DIM);
    transpose_f32_h<<<dim3(DIM / 32, DIM / 32), tblk>>>(Wk, WT + WW, DIM, DIM);
    transpose_f32_h<<<dim3(DIM / 32, DIM / 32), tblk>>>(Wv, WT + 2 * WW, DIM, DIM);

    // projections (1-term): Q written split (A of scores); K, V single
    const dim3 gproj(DIM / BN, NSEQ / BM);           // (8, 32)
    gemm_nt<0><<<gproj, blk, SMEM_BYTES(0)>>>(q16, nullptr, WT,
        nullptr, Qh, Ql, DIM, DIM, DIM, 1.0f, DIM / BK, 0, 1);
    gemm_nt<0><<<gproj, blk, SMEM_BYTES(0)>>>(k16, nullptr, WT + WW,
        nullptr, Kh, nullptr, DIM, DIM, DIM, 1.0f, DIM / BK, 0, 2);
    gemm_nt<0><<<gproj, blk, SMEM_BYTES(0)>>>(v16, nullptr, WT + 2 * WW,
        nullptr, Vr, nullptr, DIM, DIM, DIM, 1.0f, DIM / BK, 0, 2);

    // V^T
    transpose_h<<<dim3(DIM / 32, NSEQ / 32), tblk>>>(Vr, VT, NSEQ, DIM);

    // scores (2-term): S = (Q K^T)/sqrt(Dk), causal tile skip
    const dim3 gsc(NSEQ / BN, NSEQ / BM);            // (64, 32)
    gemm_nt<1><<<gsc, blk, SMEM_BYTES(1)>>>(Qh, Ql, Kh,
        S, nullptr, nullptr, DIM, DIM, NSEQ, 0.03125f, DIM / BK, 1, 0);

    // single-pass softmax -> fp16 P (zero-padded to 256 granule)
    softmax1<<<NSEQ, blk>>>(S, P);

    // O = P @ (V^T)^T (1-term), causal k-limit
    gemm_nt<0><<<gproj, blk, SMEM_BYTES(0)>>>(P, nullptr, VT,
        out, nullptr, nullptr, NSEQ, NSEQ, DIM, 1.0f, NSEQ / BK, 2, 0);
}